// round 1
// baseline (speedup 1.0000x reference)
#include <cuda_runtime.h>
#include <math_constants.h>

#define NQ        256
#define NK        50000
#define D_DIM     64
#define QT        128                       // queries per block tile
#define KT        128                       // keys per block tile
#define NKT       ((NK + KT - 1) / KT)      // 391 key tiles
#define OBS_ELEMS 3072                      // 3*32*32

// ---- static device scratch (no allocations allowed) ----
__device__ float g_cand_s[NQ * NKT * 8];
__device__ int   g_cand_i[NQ * NKT * 8];
__device__ int   g_topidx[NQ * 8];

// shared layout (floats):
//   compute phase: [0,8192) qT tile [d][col], [8192,16384) kT tile [d][col],
//                  [16384,16512) ksq per key column
//   score phase:   scores[128][129] (pad 1 -> conflict free), 16512 floats total
#define SH_K_OFF   8192
#define SH_KSQ_OFF 16384
#define SCORE_STR  129
#define SMEM_FLOATS 16512
#define SMEM_BYTES (SMEM_FLOATS * 4)        // 66048

// ---------------------------------------------------------------------------
// Kernel 1: tiled score GEMM (s = k^2 - 2*q.k) + per-tile top-8 selection
// grid: (NKT, 2), block: 256 threads, 8x8 register micro-tile per thread
// ---------------------------------------------------------------------------
__global__ __launch_bounds__(256) void knn_score_kernel(
    const float* __restrict__ qm, const float* __restrict__ km)
{
    extern __shared__ float sh[];
    const int tid = threadIdx.x;
    const int k0  = blockIdx.x * KT;
    const int q0  = blockIdx.y * QT;

    const float4* q4 = (const float4*)qm;
    const float4* k4 = (const float4*)km;

    // load q tile, transposed to [d][col]
    #pragma unroll
    for (int p = tid; p < 2048; p += 256) {
        int col = p & 127;
        int d4  = p >> 7;
        float4 v = q4[(size_t)(q0 + col) * 16 + d4];
        sh[(d4 * 4 + 0) * 128 + col] = v.x;
        sh[(d4 * 4 + 1) * 128 + col] = v.y;
        sh[(d4 * 4 + 2) * 128 + col] = v.z;
        sh[(d4 * 4 + 3) * 128 + col] = v.w;
    }
    // load k tile, transposed to [d][col]; pad OOB keys with 0
    #pragma unroll
    for (int p = tid; p < 2048; p += 256) {
        int col = p & 127;
        int d4  = p >> 7;
        int j   = k0 + col;
        float4 v = make_float4(0.f, 0.f, 0.f, 0.f);
        if (j < NK) v = k4[(size_t)j * 16 + d4];
        sh[SH_K_OFF + (d4 * 4 + 0) * 128 + col] = v.x;
        sh[SH_K_OFF + (d4 * 4 + 1) * 128 + col] = v.y;
        sh[SH_K_OFF + (d4 * 4 + 2) * 128 + col] = v.z;
        sh[SH_K_OFF + (d4 * 4 + 3) * 128 + col] = v.w;
    }
    __syncthreads();

    // per-column ||k||^2
    if (tid < 128) {
        float s = 0.f;
        #pragma unroll
        for (int d = 0; d < D_DIM; d++) {
            float v = sh[SH_K_OFF + d * 128 + tid];
            s = fmaf(v, v, s);
        }
        sh[SH_KSQ_OFF + tid] = s;
    }
    __syncthreads();

    const int qt = tid >> 4;   // 0..15
    const int kt = tid & 15;   // 0..15

    float myksq[8];
    #pragma unroll
    for (int m = 0; m < 8; m++) myksq[m] = sh[SH_KSQ_OFF + kt * 8 + m];

    float acc[8][8];
    #pragma unroll
    for (int i = 0; i < 8; i++)
        #pragma unroll
        for (int m = 0; m < 8; m++) acc[i][m] = 0.f;

    #pragma unroll 8
    for (int d = 0; d < D_DIM; d++) {
        float4 qa = *(const float4*)&sh[d * 128 + qt * 8];
        float4 qb = *(const float4*)&sh[d * 128 + qt * 8 + 4];
        float4 ka = *(const float4*)&sh[SH_K_OFF + d * 128 + kt * 8];
        float4 kb = *(const float4*)&sh[SH_K_OFF + d * 128 + kt * 8 + 4];
        float qr[8] = {qa.x, qa.y, qa.z, qa.w, qb.x, qb.y, qb.z, qb.w};
        float kr[8] = {ka.x, ka.y, ka.z, ka.w, kb.x, kb.y, kb.z, kb.w};
        #pragma unroll
        for (int i = 0; i < 8; i++)
            #pragma unroll
            for (int m = 0; m < 8; m++)
                acc[i][m] = fmaf(qr[i], kr[m], acc[i][m]);
    }
    __syncthreads();   // everyone done reading tiles before scores overwrite smem

    // write scores s = ksq - 2*dot (same per-query ordering as full d2)
    #pragma unroll
    for (int i = 0; i < 8; i++)
        #pragma unroll
        for (int m = 0; m < 8; m++)
            sh[(qt * 8 + i) * SCORE_STR + kt * 8 + m] =
                fmaf(-2.f, acc[i][m], myksq[m]);
    __syncthreads();

    // per-query top-8 within this 128-key tile
    if (tid < 128) {
        const int kvalid = (NK - k0 < KT) ? (NK - k0) : KT;
        float s8[8]; int i8[8];
        #pragma unroll
        for (int i = 0; i < 8; i++) { s8[i] = CUDART_INF_F; i8[i] = 0; }
        for (int c = 0; c < kvalid; c++) {
            float s = sh[tid * SCORE_STR + c];
            if (s < s8[7]) {
                s8[7] = s; i8[7] = k0 + c;
                #pragma unroll
                for (int t = 7; t > 0; t--) {
                    if (s8[t] < s8[t - 1]) {
                        float ts = s8[t]; s8[t] = s8[t - 1]; s8[t - 1] = ts;
                        int   ti = i8[t]; i8[t] = i8[t - 1]; i8[t - 1] = ti;
                    }
                }
            }
        }
        size_t base = ((size_t)(q0 + tid) * NKT + blockIdx.x) * 8;
        #pragma unroll
        for (int m = 0; m < 8; m++) {
            g_cand_s[base + m] = s8[m];
            g_cand_i[base + m] = i8[m];
        }
    }
}

// ---------------------------------------------------------------------------
// Kernel 2: per-query merge of NKT*8 candidates -> final top-8 (ascending d2)
// grid: NQ blocks, 128 threads
// ---------------------------------------------------------------------------
__global__ __launch_bounds__(128) void knn_merge_kernel()
{
    __shared__ float ss[128 * 8];
    __shared__ int   si[128 * 8];
    const int q   = blockIdx.x;
    const int tid = threadIdx.x;

    float s8[8]; int i8[8];
    #pragma unroll
    for (int i = 0; i < 8; i++) { s8[i] = CUDART_INF_F; i8[i] = 0; }

    for (int t = tid; t < NKT; t += 128) {
        size_t base = ((size_t)q * NKT + t) * 8;
        #pragma unroll
        for (int m = 0; m < 8; m++) {
            float s = g_cand_s[base + m];
            if (s < s8[7]) {
                int j = g_cand_i[base + m];
                s8[7] = s; i8[7] = j;
                #pragma unroll
                for (int u = 7; u > 0; u--) {
                    if (s8[u] < s8[u - 1]) {
                        float ts = s8[u]; s8[u] = s8[u - 1]; s8[u - 1] = ts;
                        int   ti = i8[u]; i8[u] = i8[u - 1]; i8[u - 1] = ti;
                    }
                }
            }
        }
    }
    #pragma unroll
    for (int m = 0; m < 8; m++) { ss[tid * 8 + m] = s8[m]; si[tid * 8 + m] = i8[m]; }

    for (int stride = 64; stride >= 1; stride >>= 1) {
        __syncthreads();
        if (tid < stride) {
            int o = (tid + stride) * 8;
            #pragma unroll
            for (int m = 0; m < 8; m++) {
                float s = ss[o + m];
                if (s < s8[7]) {
                    int j = si[o + m];
                    s8[7] = s; i8[7] = j;
                    #pragma unroll
                    for (int u = 7; u > 0; u--) {
                        if (s8[u] < s8[u - 1]) {
                            float ts = s8[u]; s8[u] = s8[u - 1]; s8[u - 1] = ts;
                            int   ti = i8[u]; i8[u] = i8[u - 1]; i8[u - 1] = ti;
                        }
                    }
                }
            }
            #pragma unroll
            for (int m = 0; m < 8; m++) { ss[tid * 8 + m] = s8[m]; si[tid * 8 + m] = i8[m]; }
        }
    }

    if (tid == 0) {
        #pragma unroll
        for (int m = 0; m < 8; m++) g_topidx[q * 8 + m] = i8[m];
    }
}

// ---------------------------------------------------------------------------
// Kernel 3: gather obs[idx] -> out [8, 256, 3072]
// grid: NQ*8 blocks, 256 threads; float4 copies (12 KB per block)
// ---------------------------------------------------------------------------
__global__ __launch_bounds__(256) void knn_gather_kernel(
    const float* __restrict__ obs, float* __restrict__ out)
{
    const int b  = blockIdx.x;      // 0..2047
    const int kk = b >> 8;          // rank 0..7
    const int q  = b & 255;         // query
    const int src = g_topidx[q * 8 + kk];

    const float4* s = (const float4*)(obs + (size_t)src * OBS_ELEMS);
    float4*       d = (float4*)(out + ((size_t)kk * NQ + q) * OBS_ELEMS);

    #pragma unroll
    for (int i = threadIdx.x; i < OBS_ELEMS / 4; i += 256)
        d[i] = s[i];
}

// ---------------------------------------------------------------------------
extern "C" void kernel_launch(void* const* d_in, const int* in_sizes, int n_in,
                              void* d_out, int out_size)
{
    const float* q   = (const float*)d_in[0];   // [256,64]
    const float* k   = (const float*)d_in[1];   // [50000,64]
    const float* obs = (const float*)d_in[2];   // [50000,3,32,32]
    float* out = (float*)d_out;                 // [8,256,3,32,32]

    cudaFuncSetAttribute(knn_score_kernel,
                         cudaFuncAttributeMaxDynamicSharedMemorySize, SMEM_BYTES);

    knn_score_kernel<<<dim3(NKT, 2), 256, SMEM_BYTES>>>(q, k);
    knn_merge_kernel<<<NQ, 128>>>();
    knn_gather_kernel<<<NQ * 8, 256>>>(obs, out);
}

// round 3
// speedup vs baseline: 1.1250x; 1.1250x over previous
#include <cuda_runtime.h>
#include <cuda_bf16.h>
#include <math_constants.h>
#include <cstdint>

#define NQ        256
#define NK        50000
#define DD        64
#define KT        128
#define NKT       391          // ceil(50000/128)
#define OBS_ELEMS 3072
#define CPT       8            // candidates per tile per query

// ---- static device scratch ----
__device__ float g_cand_s[NQ * NKT * CPT];
__device__ int   g_cand_i[NQ * NKT * CPT];
__device__ int   g_topidx[NQ * 8];

// ---- smem layout (bytes) ----
// phase 1 (GEMM):  [0,18432) qs bf16 128x72, [18432,36864) ks bf16 128x72
// phase 2 (epi):   [0,67584) scores f32 128x132 (overlays qs/ks)
// always:          [67584,68096) ksq f32 [128]
#define TSTRIDE_B  144         // 72 bf16 per row
#define SC_STRIDE  132         // floats per score row
#define SM_KS_OFF  18432
#define SM_KSQ_OFF 67584
#define SM_TOTAL   68096

// ============================ helpers ============================
__device__ __forceinline__ uint32_t smem_u32(const void* p) {
    uint32_t a;
    asm("{ .reg .u64 t; cvta.to.shared.u64 t, %1; cvt.u32.u64 %0, t; }" : "=r"(a) : "l"(p));
    return a;
}
__device__ __forceinline__ void ldsm_x4(uint32_t& r0, uint32_t& r1, uint32_t& r2,
                                        uint32_t& r3, uint32_t a) {
    asm volatile("ldmatrix.sync.aligned.m8n8.x4.shared.b16 {%0,%1,%2,%3}, [%4];"
                 : "=r"(r0), "=r"(r1), "=r"(r2), "=r"(r3) : "r"(a));
}
__device__ __forceinline__ void mma_bf16(float& c0, float& c1, float& c2, float& c3,
                                         uint32_t a0, uint32_t a1, uint32_t a2, uint32_t a3,
                                         uint32_t b0, uint32_t b1) {
    asm volatile("mma.sync.aligned.m16n8k16.row.col.f32.bf16.bf16.f32 "
                 "{%0,%1,%2,%3},{%4,%5,%6,%7},{%8,%9},{%0,%1,%2,%3};"
                 : "+f"(c0), "+f"(c1), "+f"(c2), "+f"(c3)
                 : "r"(a0), "r"(a1), "r"(a2), "r"(a3), "r"(b0), "r"(b1));
}

// convert one 32-float chunk of a row to bf16 in a 144B-stride tile
__device__ __forceinline__ void store_row_bf16(char* dst_row_half,
                                               const float* __restrict__ src) {
    const float4* s = (const float4*)src;
    uint2* d = (uint2*)dst_row_half;
    #pragma unroll
    for (int i = 0; i < 8; i++) {
        float4 v = s[i];
        __nv_bfloat162 p0 = __floats2bfloat162_rn(v.x, v.y);
        __nv_bfloat162 p1 = __floats2bfloat162_rn(v.z, v.w);
        uint2 u;
        u.x = *(uint32_t*)&p0;
        u.y = *(uint32_t*)&p1;
        d[i] = u;
    }
}

// ======================================================================
// Kernel 1: bf16 mma.sync score GEMM + per-tile top-8 approx select
// grid (391, 2), 256 threads (8 warps, 4x2 warp tile grid)
// ======================================================================
__global__ __launch_bounds__(256) void knn_score_mma(
    const float* __restrict__ qm, const float* __restrict__ km)
{
    extern __shared__ char smem[];
    const uint32_t sb = smem_u32(smem);
    const int tid  = threadIdx.x;
    const int wid  = tid >> 5;
    const int lane = tid & 31;
    const int k0   = blockIdx.x * KT;
    const int q0   = blockIdx.y * 128;

    float* ksq = (float*)(smem + SM_KSQ_OFF);

    // ---- load q tile (bf16) and k tile (bf16 + fp32 ksq) ----
    {
        const int row = tid >> 1, hf = tid & 1;
        // q
        store_row_bf16(smem + row * TSTRIDE_B + hf * 64,
                       qm + (size_t)(q0 + row) * DD + hf * 32);
        // k
        const int j = k0 + row;
        char* krow = smem + SM_KS_OFF + row * TSTRIDE_B + hf * 64;
        float ss = 0.f;
        if (j < NK) {
            const float* src = km + (size_t)j * DD + hf * 32;
            store_row_bf16(krow, src);
            const float4* s4 = (const float4*)src;
            #pragma unroll
            for (int i = 0; i < 8; i++) {
                float4 v = s4[i];
                ss = fmaf(v.x, v.x, ss); ss = fmaf(v.y, v.y, ss);
                ss = fmaf(v.z, v.z, ss); ss = fmaf(v.w, v.w, ss);
            }
        } else {
            uint2* d = (uint2*)krow;
            #pragma unroll
            for (int i = 0; i < 8; i++) d[i] = make_uint2(0u, 0u);
        }
        float tot = ss + __shfl_xor_sync(0xFFFFFFFFu, ss, 1);
        if (hf == 0) ksq[row] = (j < NK) ? tot : CUDART_INF_F;
    }
    __syncthreads();

    // ---- warp GEMM: 32(m) x 64(n) per warp ----
    const int mrow = wid >> 1;          // 0..3
    const int ncol = wid & 1;           // 0..1
    const uint32_t qs_b = sb;
    const uint32_t ks_b = sb + SM_KS_OFF;

    float acc[2][8][4];
    #pragma unroll
    for (int mt = 0; mt < 2; mt++)
        #pragma unroll
        for (int nt = 0; nt < 8; nt++)
            #pragma unroll
            for (int c = 0; c < 4; c++) acc[mt][nt][c] = 0.f;

    #pragma unroll
    for (int ks16 = 0; ks16 < 4; ks16++) {
        const uint32_t dby = ks16 * 32;         // 16 bf16 = 32 bytes
        // A fragments: rows mrow*32 + mt*16 + (lane&15), col byte dby + (lane>>4)*16
        uint32_t a[2][4];
        #pragma unroll
        for (int mt = 0; mt < 2; mt++) {
            uint32_t addr = qs_b
                + (uint32_t)(mrow * 32 + mt * 16 + (lane & 15)) * TSTRIDE_B
                + dby + ((lane >> 4) << 4);
            ldsm_x4(a[mt][0], a[mt][1], a[mt][2], a[mt][3], addr);
        }
        // B fragments: 4 x ldmatrix.x4, each covers two n8 tiles
        uint32_t b[8][2];
        #pragma unroll
        for (int np = 0; np < 4; np++) {
            uint32_t n = (uint32_t)(ncol * 64 + np * 16 + ((lane >> 4) << 3) + (lane & 7));
            uint32_t addr = ks_b + n * TSTRIDE_B + dby + (((lane >> 3) & 1) << 4);
            ldsm_x4(b[np * 2][0], b[np * 2][1], b[np * 2 + 1][0], b[np * 2 + 1][1], addr);
        }
        #pragma unroll
        for (int mt = 0; mt < 2; mt++)
            #pragma unroll
            for (int nt = 0; nt < 8; nt++)
                mma_bf16(acc[mt][nt][0], acc[mt][nt][1], acc[mt][nt][2], acc[mt][nt][3],
                         a[mt][0], a[mt][1], a[mt][2], a[mt][3],
                         b[nt][0], b[nt][1]);
    }
    __syncthreads();   // done reading qs/ks; scores may overwrite

    // ---- epilogue: s = ksq - 2*dot into smem scores ----
    float* sc = (float*)smem;
    {
        const int g = lane >> 2, t = lane & 3;
        #pragma unroll
        for (int mt = 0; mt < 2; mt++) {
            const int r0 = mrow * 32 + mt * 16 + g;
            #pragma unroll
            for (int nt = 0; nt < 8; nt++) {
                const int col = ncol * 64 + nt * 8 + t * 2;
                const float kq0 = ksq[col], kq1 = ksq[col + 1];
                float2 v0 = make_float2(fmaf(-2.f, acc[mt][nt][0], kq0),
                                        fmaf(-2.f, acc[mt][nt][1], kq1));
                float2 v1 = make_float2(fmaf(-2.f, acc[mt][nt][2], kq0),
                                        fmaf(-2.f, acc[mt][nt][3], kq1));
                *(float2*)&sc[(size_t)r0 * SC_STRIDE + col]       = v0;
                *(float2*)&sc[(size_t)(r0 + 8) * SC_STRIDE + col] = v1;
            }
        }
    }
    __syncthreads();

    // ---- per-query top-8 within this 128-key tile ----
    if (tid < 128) {
        float l0 = CUDART_INF_F, l1 = CUDART_INF_F, l2 = CUDART_INF_F, l3 = CUDART_INF_F;
        float l4 = CUDART_INF_F, l5 = CUDART_INF_F, l6 = CUDART_INF_F, l7 = CUDART_INF_F;
        int   i0 = 0, i1 = 0, i2 = 0, i3 = 0, i4 = 0, i5 = 0, i6 = 0, i7 = 0;
        const float* row = &sc[(size_t)tid * SC_STRIDE];
        #pragma unroll 4
        for (int c = 0; c < KT; c++) {
            float s = row[c];
            if (s < l7) {
                int ix = k0 + c;
                l7 = s; i7 = ix;
                if (l7 < l6) { float t_ = l7; l7 = l6; l6 = t_; int u = i7; i7 = i6; i6 = u; }
                if (l6 < l5) { float t_ = l6; l6 = l5; l5 = t_; int u = i6; i6 = i5; i5 = u; }
                if (l5 < l4) { float t_ = l5; l5 = l4; l4 = t_; int u = i5; i5 = i4; i4 = u; }
                if (l4 < l3) { float t_ = l4; l4 = l3; l3 = t_; int u = i4; i4 = i3; i3 = u; }
                if (l3 < l2) { float t_ = l3; l3 = l2; l2 = t_; int u = i3; i3 = i2; i2 = u; }
                if (l2 < l1) { float t_ = l2; l2 = l1; l1 = t_; int u = i2; i2 = i1; i1 = u; }
                if (l1 < l0) { float t_ = l1; l1 = l0; l0 = t_; int u = i1; i1 = i0; i0 = u; }
            }
        }
        size_t base = ((size_t)(q0 + tid) * NKT + blockIdx.x) * CPT;
        g_cand_s[base + 0] = l0; g_cand_i[base + 0] = i0;
        g_cand_s[base + 1] = l1; g_cand_i[base + 1] = i1;
        g_cand_s[base + 2] = l2; g_cand_i[base + 2] = i2;
        g_cand_s[base + 3] = l3; g_cand_i[base + 3] = i3;
        g_cand_s[base + 4] = l4; g_cand_i[base + 4] = i4;
        g_cand_s[base + 5] = l5; g_cand_i[base + 5] = i5;
        g_cand_s[base + 6] = l6; g_cand_i[base + 6] = i6;
        g_cand_s[base + 7] = l7; g_cand_i[base + 7] = i7;
    }
}

// ======================================================================
// Kernel 2: merge 391*8 approx candidates -> top-16 -> exact fp32
//           rescore -> exact top-8. grid NQ, 128 threads.
// ======================================================================
#define MERGE_INS(s_, j_)                                                       \
    if ((s_) < l[15]) {                                                          \
        l[15] = (s_); li[15] = (j_);                                             \
        _Pragma("unroll")                                                        \
        for (int u = 15; u > 0; u--)                                             \
            if (l[u] < l[u-1]) { float ts = l[u]; l[u] = l[u-1]; l[u-1] = ts;    \
                                 int ti = li[u]; li[u] = li[u-1]; li[u-1] = ti; }\
    }

__global__ __launch_bounds__(128) void knn_merge_rescore(
    const float* __restrict__ qm, const float* __restrict__ km)
{
    __shared__ float ss[128 * 16];
    __shared__ int   si[128 * 16];
    __shared__ float ex[16];
    __shared__ int   exi[16];
    const int q = blockIdx.x, tid = threadIdx.x;
    const int TOT = NKT * CPT;   // 3128

    float l[16]; int li[16];
    #pragma unroll
    for (int i = 0; i < 16; i++) { l[i] = CUDART_INF_F; li[i] = -1; }

    const size_t qb = (size_t)q * TOT;
    for (int e = tid; e < TOT; e += 128) {
        float s = g_cand_s[qb + e];
        int   j = g_cand_i[qb + e];
        MERGE_INS(s, j);
    }
    #pragma unroll
    for (int m = 0; m < 16; m++) { ss[tid * 16 + m] = l[m]; si[tid * 16 + m] = li[m]; }

    for (int stride = 64; stride >= 1; stride >>= 1) {
        __syncthreads();
        if (tid < stride) {
            const int o = (tid + stride) * 16;
            #pragma unroll
            for (int m = 0; m < 16; m++) {
                float s = ss[o + m]; int j = si[o + m];
                MERGE_INS(s, j);
            }
            #pragma unroll
            for (int m = 0; m < 16; m++) { ss[tid * 16 + m] = l[m]; si[tid * 16 + m] = li[m]; }
        }
    }
    __syncthreads();
    // thread 0's top-16 sits in ss/si[0..16)

    // exact fp32 rescore: 16 candidates x 8 lanes each
    {
        const int c = tid >> 3, lo = tid & 7;
        const int idx = si[c];
        float d = 0.f;
        if (idx >= 0) {
            const float* qr = qm + (size_t)q * DD + lo * 8;
            const float* kr = km + (size_t)idx * DD + lo * 8;
            #pragma unroll
            for (int d8 = 0; d8 < 8; d8++) {
                float df = qr[d8] - kr[d8];
                d = fmaf(df, df, d);
            }
        } else d = CUDART_INF_F;
        d += __shfl_xor_sync(0xFFFFFFFFu, d, 4);
        d += __shfl_xor_sync(0xFFFFFFFFu, d, 2);
        d += __shfl_xor_sync(0xFFFFFFFFu, d, 1);
        if (lo == 0) { ex[c] = d; exi[c] = idx; }
    }
    __syncthreads();

    if (tid == 0) {
        float es[16]; int ei[16];
        #pragma unroll
        for (int m = 0; m < 16; m++) { es[m] = ex[m]; ei[m] = exi[m]; }
        // insertion sort ascending by (d2, idx)
        #pragma unroll
        for (int a = 1; a < 16; a++)
            #pragma unroll
            for (int b = 16 - 1; b >= 1; b--)
                if (es[b] < es[b-1] || (es[b] == es[b-1] && ei[b] < ei[b-1])) {
                    float ts = es[b]; es[b] = es[b-1]; es[b-1] = ts;
                    int ti = ei[b]; ei[b] = ei[b-1]; ei[b-1] = ti;
                }
        #pragma unroll
        for (int m = 0; m < 8; m++) g_topidx[q * 8 + m] = ei[m];
    }
}

// ======================================================================
// Kernel 3: gather obs[idx] -> out [8, 256, 3072]
// ======================================================================
__global__ __launch_bounds__(256) void knn_gather_kernel(
    const float* __restrict__ obs, float* __restrict__ out)
{
    const int b  = blockIdx.x;
    const int kk = b >> 8;
    const int q  = b & 255;
    const int src = g_topidx[q * 8 + kk];

    const float4* s = (const float4*)(obs + (size_t)src * OBS_ELEMS);
    float4*       d = (float4*)(out + ((size_t)kk * NQ + q) * OBS_ELEMS);

    #pragma unroll
    for (int i = threadIdx.x; i < OBS_ELEMS / 4; i += 256)
        d[i] = s[i];
}

// ======================================================================
extern "C" void kernel_launch(void* const* d_in, const int* in_sizes, int n_in,
                              void* d_out, int out_size)
{
    const float* q   = (const float*)d_in[0];
    const float* k   = (const float*)d_in[1];
    const float* obs = (const float*)d_in[2];
    float* out = (float*)d_out;

    cudaFuncSetAttribute(knn_score_mma,
                         cudaFuncAttributeMaxDynamicSharedMemorySize, SM_TOTAL);

    knn_score_mma<<<dim3(NKT, 2), 256, SM_TOTAL>>>(q, k);
    knn_merge_rescore<<<NQ, 128>>>(q, k);
    knn_gather_kernel<<<NQ * 8, 256>>>(obs, out);
}

// round 4
// speedup vs baseline: 1.1736x; 1.0432x over previous
#include <cuda_runtime.h>
#include <cuda_bf16.h>
#include <math_constants.h>
#include <cstdint>

#define NQ        256
#define NK        50000
#define DD        64
#define KT        128
#define NKT       391          // ceil(50000/128)
#define OBS_ELEMS 3072
#define CPT       16           // candidates per tile per query (2 halves x 8)
#define NGROUPS   (NKT * 2)    // 782 sorted 8-groups per query

// ---- static device scratch ----
__device__ float2 g_cand[NQ * NKT * CPT];   // (score, idx-as-float-bits)
__device__ int    g_topidx[NQ * 8];

// ---- smem layout (bytes) ----
// operands (GEMM phase): qs bf16 128x72 @ [0,18432), ks bf16 128x72 @ [18432,36864)
// scores   (epilogue):   128 rows x 544 B (two 64-f32 halves at +0 / +272), overlays operands
// ksq:                   [69632, 70144)
#define TSTRIDE_B  144         // operand row stride (72 bf16)
#define SC_ROW_B   544         // score row stride bytes (conflict-free for f4 scan)
#define SC_HALF_B  272         // byte offset of col-64..127 half within a row
#define SM_KS_OFF  18432
#define SM_KSQ_OFF 69632
#define SM_TOTAL   70144

// ============================ helpers ============================
__device__ __forceinline__ uint32_t smem_u32(const void* p) {
    uint32_t a;
    asm("{ .reg .u64 t; cvta.to.shared.u64 t, %1; cvt.u32.u64 %0, t; }" : "=r"(a) : "l"(p));
    return a;
}
__device__ __forceinline__ void ldsm_x4(uint32_t& r0, uint32_t& r1, uint32_t& r2,
                                        uint32_t& r3, uint32_t a) {
    asm volatile("ldmatrix.sync.aligned.m8n8.x4.shared.b16 {%0,%1,%2,%3}, [%4];"
                 : "=r"(r0), "=r"(r1), "=r"(r2), "=r"(r3) : "r"(a));
}
__device__ __forceinline__ void mma_bf16(float& c0, float& c1, float& c2, float& c3,
                                         uint32_t a0, uint32_t a1, uint32_t a2, uint32_t a3,
                                         uint32_t b0, uint32_t b1) {
    asm volatile("mma.sync.aligned.m16n8k16.row.col.f32.bf16.bf16.f32 "
                 "{%0,%1,%2,%3},{%4,%5,%6,%7},{%8,%9},{%0,%1,%2,%3};"
                 : "+f"(c0), "+f"(c1), "+f"(c2), "+f"(c3)
                 : "r"(a0), "r"(a1), "r"(a2), "r"(a3), "r"(b0), "r"(b1));
}

__device__ __forceinline__ void store_row_bf16(char* dst_row_half,
                                               const float* __restrict__ src) {
    const float4* s = (const float4*)src;
    uint2* d = (uint2*)dst_row_half;
    #pragma unroll
    for (int i = 0; i < 8; i++) {
        float4 v = s[i];
        __nv_bfloat162 p0 = __floats2bfloat162_rn(v.x, v.y);
        __nv_bfloat162 p1 = __floats2bfloat162_rn(v.z, v.w);
        uint2 u;
        u.x = *(uint32_t*)&p0;
        u.y = *(uint32_t*)&p1;
        d[i] = u;
    }
}

// 8-deep ascending insertion (l0 smallest .. l7 = 8th)
#define INS8(s_, ix_)                                                            \
    if ((s_) < l7) {                                                             \
        l7 = (s_); i7 = (ix_);                                                   \
        if (l7 < l6) { float t_=l7; l7=l6; l6=t_; int u_=i7; i7=i6; i6=u_; }      \
        if (l6 < l5) { float t_=l6; l6=l5; l5=t_; int u_=i6; i6=i5; i5=u_; }      \
        if (l5 < l4) { float t_=l5; l5=l4; l4=t_; int u_=i5; i5=i4; i4=u_; }      \
        if (l4 < l3) { float t_=l4; l4=l3; l3=t_; int u_=i4; i4=i3; i3=u_; }      \
        if (l3 < l2) { float t_=l3; l3=l2; l2=t_; int u_=i3; i3=i2; i2=u_; }      \
        if (l2 < l1) { float t_=l2; l2=l1; l1=t_; int u_=i2; i2=i1; i1=u_; }      \
        if (l1 < l0) { float t_=l1; l1=l0; l0=t_; int u_=i1; i1=i0; i0=u_; }      \
    }

// ======================================================================
// Kernel 1: bf16 mma.sync score GEMM + per-(tile,half) top-8 select
// grid (391, 2), 256 threads (8 warps, 4x2 warp tile grid)
// ======================================================================
__global__ __launch_bounds__(256) void knn_score_mma(
    const float* __restrict__ qm, const float* __restrict__ km)
{
    extern __shared__ char smem[];
    const uint32_t sb = smem_u32(smem);
    const int tid  = threadIdx.x;
    const int wid  = tid >> 5;
    const int lane = tid & 31;
    const int k0   = blockIdx.x * KT;
    const int q0   = blockIdx.y * 128;

    float* ksq = (float*)(smem + SM_KSQ_OFF);

    // ---- load q tile (bf16) and k tile (bf16 + fp32 ksq) ----
    {
        const int row = tid >> 1, hf = tid & 1;
        store_row_bf16(smem + row * TSTRIDE_B + hf * 64,
                       qm + (size_t)(q0 + row) * DD + hf * 32);
        const int j = k0 + row;
        char* krow = smem + SM_KS_OFF + row * TSTRIDE_B + hf * 64;
        float ss = 0.f;
        if (j < NK) {
            const float* src = km + (size_t)j * DD + hf * 32;
            store_row_bf16(krow, src);
            const float4* s4 = (const float4*)src;
            #pragma unroll
            for (int i = 0; i < 8; i++) {
                float4 v = s4[i];
                ss = fmaf(v.x, v.x, ss); ss = fmaf(v.y, v.y, ss);
                ss = fmaf(v.z, v.z, ss); ss = fmaf(v.w, v.w, ss);
            }
        } else {
            uint2* d = (uint2*)krow;
            #pragma unroll
            for (int i = 0; i < 8; i++) d[i] = make_uint2(0u, 0u);
        }
        float tot = ss + __shfl_xor_sync(0xFFFFFFFFu, ss, 1);
        if (hf == 0) ksq[row] = (j < NK) ? tot : CUDART_INF_F;
    }
    __syncthreads();

    // ---- warp GEMM: 32(m) x 64(n) per warp ----
    const int mrow = wid >> 1;          // 0..3
    const int ncol = wid & 1;           // 0..1
    const uint32_t qs_b = sb;
    const uint32_t ks_b = sb + SM_KS_OFF;

    float acc[2][8][4];
    #pragma unroll
    for (int mt = 0; mt < 2; mt++)
        #pragma unroll
        for (int nt = 0; nt < 8; nt++)
            #pragma unroll
            for (int c = 0; c < 4; c++) acc[mt][nt][c] = 0.f;

    #pragma unroll
    for (int ks16 = 0; ks16 < 4; ks16++) {
        const uint32_t dby = ks16 * 32;
        uint32_t a[2][4];
        #pragma unroll
        for (int mt = 0; mt < 2; mt++) {
            uint32_t addr = qs_b
                + (uint32_t)(mrow * 32 + mt * 16 + (lane & 15)) * TSTRIDE_B
                + dby + ((lane >> 4) << 4);
            ldsm_x4(a[mt][0], a[mt][1], a[mt][2], a[mt][3], addr);
        }
        uint32_t b[8][2];
        #pragma unroll
        for (int np = 0; np < 4; np++) {
            uint32_t n = (uint32_t)(ncol * 64 + np * 16 + ((lane >> 4) << 3) + (lane & 7));
            uint32_t addr = ks_b + n * TSTRIDE_B + dby + (((lane >> 3) & 1) << 4);
            ldsm_x4(b[np * 2][0], b[np * 2][1], b[np * 2 + 1][0], b[np * 2 + 1][1], addr);
        }
        #pragma unroll
        for (int mt = 0; mt < 2; mt++)
            #pragma unroll
            for (int nt = 0; nt < 8; nt++)
                mma_bf16(acc[mt][nt][0], acc[mt][nt][1], acc[mt][nt][2], acc[mt][nt][3],
                         a[mt][0], a[mt][1], a[mt][2], a[mt][3],
                         b[nt][0], b[nt][1]);
    }
    __syncthreads();   // done reading qs/ks; scores overwrite

    // ---- epilogue: s = ksq - 2*dot into smem score tile ----
    {
        const int g = lane >> 2, t = lane & 3;
        const uint32_t hoff = ncol ? 16u : 0u;   // half-gap correction
        #pragma unroll
        for (int mt = 0; mt < 2; mt++) {
            const int r0 = mrow * 32 + mt * 16 + g;
            #pragma unroll
            for (int nt = 0; nt < 8; nt++) {
                const int col = ncol * 64 + nt * 8 + t * 2;
                const float kq0 = ksq[col], kq1 = ksq[col + 1];
                float2 v0 = make_float2(fmaf(-2.f, acc[mt][nt][0], kq0),
                                        fmaf(-2.f, acc[mt][nt][1], kq1));
                float2 v1 = make_float2(fmaf(-2.f, acc[mt][nt][2], kq0),
                                        fmaf(-2.f, acc[mt][nt][3], kq1));
                *(float2*)(smem + (uint32_t)r0 * SC_ROW_B + (uint32_t)col * 4 + hoff) = v0;
                *(float2*)(smem + (uint32_t)(r0 + 8) * SC_ROW_B + (uint32_t)col * 4 + hoff) = v1;
            }
        }
    }
    __syncthreads();

    // ---- all 256 threads: per-(query,half) top-8 over 64 scores ----
    {
        const int row = tid >> 1, hf = tid & 1;
        const float4* rp = (const float4*)(smem + (uint32_t)row * SC_ROW_B + hf * SC_HALF_B);
        const int cbase = k0 + hf * 64;

        float l0 = CUDART_INF_F, l1 = CUDART_INF_F, l2 = CUDART_INF_F, l3 = CUDART_INF_F;
        float l4 = CUDART_INF_F, l5 = CUDART_INF_F, l6 = CUDART_INF_F, l7 = CUDART_INF_F;
        int   i0 = 0, i1 = 0, i2 = 0, i3 = 0, i4 = 0, i5 = 0, i6 = 0, i7 = 0;

        #pragma unroll
        for (int i = 0; i < 16; i++) {
            float4 v = rp[i];
            const int c = cbase + i * 4;
            INS8(v.x, c);
            INS8(v.y, c + 1);
            INS8(v.z, c + 2);
            INS8(v.w, c + 3);
        }

        float2* dst = &g_cand[((size_t)(q0 + row) * NKT + blockIdx.x) * CPT + hf * 8];
        dst[0] = make_float2(l0, __int_as_float(i0));
        dst[1] = make_float2(l1, __int_as_float(i1));
        dst[2] = make_float2(l2, __int_as_float(i2));
        dst[3] = make_float2(l3, __int_as_float(i3));
        dst[4] = make_float2(l4, __int_as_float(i4));
        dst[5] = make_float2(l5, __int_as_float(i5));
        dst[6] = make_float2(l6, __int_as_float(i6));
        dst[7] = make_float2(l7, __int_as_float(i7));
    }
}

// ======================================================================
// Kernel 2: merge 782 sorted 8-groups -> top-16 approx -> exact fp32
//           rescore -> exact top-8. grid NQ, 128 threads.
// ======================================================================
#define MERGE_INS16(s_, j_)                                                      \
    {                                                                            \
        l[15] = (s_); li[15] = (j_);                                             \
        _Pragma("unroll")                                                        \
        for (int u = 15; u > 0; u--)                                             \
            if (l[u] < l[u-1]) { float ts = l[u]; l[u] = l[u-1]; l[u-1] = ts;    \
                                 int ti = li[u]; li[u] = li[u-1]; li[u-1] = ti; }\
    }

__global__ __launch_bounds__(128) void knn_merge_rescore(
    const float* __restrict__ qm, const float* __restrict__ km)
{
    __shared__ float ss[128 * 16];
    __shared__ int   si[128 * 16];
    __shared__ float ex[16];
    __shared__ int   exi[16];
    const int q = blockIdx.x, tid = threadIdx.x;

    float l[16]; int li[16];
    #pragma unroll
    for (int i = 0; i < 16; i++) { l[i] = CUDART_INF_F; li[i] = -1; }

    const size_t qb = (size_t)q * NKT * CPT;
    for (int g = tid; g < NGROUPS; g += 128) {
        const float2* cp = &g_cand[qb + (size_t)g * 8];
        #pragma unroll 1
        for (int m = 0; m < 8; m++) {
            float2 c = cp[m];
            if (c.x >= l[15]) break;          // group sorted ascending
            MERGE_INS16(c.x, __float_as_int(c.y));
        }
    }
    #pragma unroll
    for (int m = 0; m < 16; m++) { ss[tid * 16 + m] = l[m]; si[tid * 16 + m] = li[m]; }

    for (int stride = 64; stride >= 1; stride >>= 1) {
        __syncthreads();
        if (tid < stride) {
            const int o = (tid + stride) * 16;
            #pragma unroll 1
            for (int m = 0; m < 16; m++) {         // other list sorted ascending
                float s = ss[o + m];
                if (s >= l[15]) break;
                MERGE_INS16(s, si[o + m]);
            }
            #pragma unroll
            for (int m = 0; m < 16; m++) { ss[tid * 16 + m] = l[m]; si[tid * 16 + m] = li[m]; }
        }
    }
    __syncthreads();
    // thread 0's top-16 sits in ss/si[0..16)

    // exact fp32 rescore: 16 candidates x 8 lanes each
    {
        const int c = tid >> 3, lo = tid & 7;
        const int idx = si[c];
        float d = 0.f;
        if (idx >= 0) {
            const float* qr = qm + (size_t)q * DD + lo * 8;
            const float* kr = km + (size_t)idx * DD + lo * 8;
            #pragma unroll
            for (int d8 = 0; d8 < 8; d8++) {
                float df = qr[d8] - kr[d8];
                d = fmaf(df, df, d);
            }
        } else d = CUDART_INF_F;
        d += __shfl_xor_sync(0xFFFFFFFFu, d, 4);
        d += __shfl_xor_sync(0xFFFFFFFFu, d, 2);
        d += __shfl_xor_sync(0xFFFFFFFFu, d, 1);
        if (lo == 0) { ex[c] = d; exi[c] = idx; }
    }
    __syncthreads();

    if (tid == 0) {
        float es[16]; int ei[16];
        #pragma unroll
        for (int m = 0; m < 16; m++) { es[m] = ex[m]; ei[m] = exi[m]; }
        #pragma unroll
        for (int a = 1; a < 16; a++)
            #pragma unroll
            for (int b = 16 - 1; b >= 1; b--)
                if (es[b] < es[b-1] || (es[b] == es[b-1] && ei[b] < ei[b-1])) {
                    float ts = es[b]; es[b] = es[b-1]; es[b-1] = ts;
                    int ti = ei[b]; ei[b] = ei[b-1]; ei[b-1] = ti;
                }
        #pragma unroll
        for (int m = 0; m < 8; m++) g_topidx[q * 8 + m] = ei[m];
    }
}

// ======================================================================
// Kernel 3: gather obs[idx] -> out [8, 256, 3072]
// ======================================================================
__global__ __launch_bounds__(256) void knn_gather_kernel(
    const float* __restrict__ obs, float* __restrict__ out)
{
    const int b  = blockIdx.x;
    const int kk = b >> 8;
    const int q  = b & 255;
    const int src = g_topidx[q * 8 + kk];

    const float4* s = (const float4*)(obs + (size_t)src * OBS_ELEMS);
    float4*       d = (float4*)(out + ((size_t)kk * NQ + q) * OBS_ELEMS);

    #pragma unroll
    for (int i = threadIdx.x; i < OBS_ELEMS / 4; i += 256)
        d[i] = s[i];
}

// ======================================================================
extern "C" void kernel_launch(void* const* d_in, const int* in_sizes, int n_in,
                              void* d_out, int out_size)
{
    const float* q   = (const float*)d_in[0];
    const float* k   = (const float*)d_in[1];
    const float* obs = (const float*)d_in[2];
    float* out = (float*)d_out;

    cudaFuncSetAttribute(knn_score_mma,
                         cudaFuncAttributeMaxDynamicSharedMemorySize, SM_TOTAL);

    knn_score_mma<<<dim3(NKT, 2), 256, SM_TOTAL>>>(q, k);
    knn_merge_rescore<<<NQ, 128>>>(q, k);
    knn_gather_kernel<<<NQ * 8, 256>>>(obs, out);
}

// round 5
// speedup vs baseline: 1.6998x; 1.4483x over previous
#include <cuda_runtime.h>
#include <cuda_bf16.h>
#include <math_constants.h>
#include <cstdint>

#define NQ        256
#define NK        50000
#define DD        64
#define KT        128
#define NKT       391          // ceil(50000/128)
#define NHALF     782          // 64-key halves
#define NHP       784          // padded row width of g_hmin
#define OBS_ELEMS 3072
#define CAP       64           // max candidate halves per query
#define MARGIN    0.05f        // >> 2x split-bf16 score error bound

// ---- static device scratch ----
__device__ float g_hmin[NQ * NHP];      // per-(query, half) min approx score
__device__ int   g_candlist[NQ * CAP];
__device__ int   g_candcnt[NQ];
__device__ int   g_topidx[NQ * 8];

// ---- kernel-1 smem layout (bytes): 4 operand tiles 128x72 bf16 + ksq ----
#define TSTRIDE_B  144
#define SM_QHI 0
#define SM_QLO 18432
#define SM_KHI 36864
#define SM_KLO 55296
#define SM_KSQ 73728
#define SM_TOTAL 74240

// ============================ helpers ============================
__device__ __forceinline__ uint32_t smem_u32(const void* p) {
    uint32_t a;
    asm("{ .reg .u64 t; cvta.to.shared.u64 t, %1; cvt.u32.u64 %0, t; }" : "=r"(a) : "l"(p));
    return a;
}
__device__ __forceinline__ void ldsm_x4(uint32_t& r0, uint32_t& r1, uint32_t& r2,
                                        uint32_t& r3, uint32_t a) {
    asm volatile("ldmatrix.sync.aligned.m8n8.x4.shared.b16 {%0,%1,%2,%3}, [%4];"
                 : "=r"(r0), "=r"(r1), "=r"(r2), "=r"(r3) : "r"(a));
}
__device__ __forceinline__ void mma_bf16(float& c0, float& c1, float& c2, float& c3,
                                         uint32_t a0, uint32_t a1, uint32_t a2, uint32_t a3,
                                         uint32_t b0, uint32_t b1) {
    asm volatile("mma.sync.aligned.m16n8k16.row.col.f32.bf16.bf16.f32 "
                 "{%0,%1,%2,%3},{%4,%5,%6,%7},{%8,%9},{%0,%1,%2,%3};"
                 : "+f"(c0), "+f"(c1), "+f"(c2), "+f"(c3)
                 : "r"(a0), "r"(a1), "r"(a2), "r"(a3), "r"(b0), "r"(b1));
}

// split one 32-float chunk into hi/lo bf16 rows
__device__ __forceinline__ void store_row_split(char* dhi, char* dlo,
                                                const float* __restrict__ src) {
    const float4* s = (const float4*)src;
    uint2* ph = (uint2*)dhi;
    uint2* pl = (uint2*)dlo;
    #pragma unroll
    for (int i = 0; i < 8; i++) {
        float4 v = s[i];
        __nv_bfloat16 h0 = __float2bfloat16(v.x), h1 = __float2bfloat16(v.y);
        __nv_bfloat16 h2 = __float2bfloat16(v.z), h3 = __float2bfloat16(v.w);
        __nv_bfloat16 l0 = __float2bfloat16(v.x - __bfloat162float(h0));
        __nv_bfloat16 l1 = __float2bfloat16(v.y - __bfloat162float(h1));
        __nv_bfloat16 l2 = __float2bfloat16(v.z - __bfloat162float(h2));
        __nv_bfloat16 l3 = __float2bfloat16(v.w - __bfloat162float(h3));
        __nv_bfloat162 hh0 = __halves2bfloat162(h0, h1), hh1 = __halves2bfloat162(h2, h3);
        __nv_bfloat162 ll0 = __halves2bfloat162(l0, l1), ll1 = __halves2bfloat162(l2, l3);
        uint2 uh, ul;
        uh.x = *(uint32_t*)&hh0; uh.y = *(uint32_t*)&hh1;
        ul.x = *(uint32_t*)&ll0; ul.y = *(uint32_t*)&ll1;
        ph[i] = uh; pl[i] = ul;
    }
}

// 8-deep ascending insert with (s, idx) lexicographic tie-break
#define INS8T(s_, j_)                                                            \
    if ((s_) < l[7] || ((s_) == l[7] && (j_) < li[7])) {                         \
        l[7] = (s_); li[7] = (j_);                                               \
        _Pragma("unroll")                                                        \
        for (int u = 7; u > 0; u--)                                              \
            if (l[u] < l[u-1] || (l[u] == l[u-1] && li[u] < li[u-1])) {          \
                float ts = l[u]; l[u] = l[u-1]; l[u-1] = ts;                     \
                int ti = li[u]; li[u] = li[u-1]; li[u-1] = ti; }                 \
    }

// ======================================================================
// Kernel 1: split-bf16 mma.sync score GEMM -> per-(query,half) MIN only
// grid (391, 2), 256 threads (8 warps: 4 m-rows x 2 n-cols)
// ======================================================================
__global__ __launch_bounds__(256) void knn_score_min(
    const float* __restrict__ qm, const float* __restrict__ km)
{
    extern __shared__ char smem[];
    const uint32_t sb = smem_u32(smem);
    const int tid  = threadIdx.x;
    const int wid  = tid >> 5;
    const int lane = tid & 31;
    const int k0   = blockIdx.x * KT;
    const int q0   = blockIdx.y * 128;

    float* ksq = (float*)(smem + SM_KSQ);

    // ---- load & split q/k tiles, compute ksq ----
    {
        const int row = tid >> 1, hf = tid & 1;
        store_row_split(smem + SM_QHI + row * TSTRIDE_B + hf * 64,
                        smem + SM_QLO + row * TSTRIDE_B + hf * 64,
                        qm + (size_t)(q0 + row) * DD + hf * 32);
        const int j = k0 + row;
        char* khi = smem + SM_KHI + row * TSTRIDE_B + hf * 64;
        char* klo = smem + SM_KLO + row * TSTRIDE_B + hf * 64;
        float ss = 0.f;
        if (j < NK) {
            const float* src = km + (size_t)j * DD + hf * 32;
            store_row_split(khi, klo, src);
            const float4* s4 = (const float4*)src;
            #pragma unroll
            for (int i = 0; i < 8; i++) {
                float4 v = s4[i];
                ss = fmaf(v.x, v.x, ss); ss = fmaf(v.y, v.y, ss);
                ss = fmaf(v.z, v.z, ss); ss = fmaf(v.w, v.w, ss);
            }
        } else {
            uint2 z = make_uint2(0u, 0u);
            uint2* dh = (uint2*)khi; uint2* dl = (uint2*)klo;
            #pragma unroll
            for (int i = 0; i < 8; i++) { dh[i] = z; dl[i] = z; }
        }
        float tot = ss + __shfl_xor_sync(0xFFFFFFFFu, ss, 1);
        if (hf == 0) ksq[row] = (j < NK) ? tot : CUDART_INF_F;
    }
    __syncthreads();

    // ---- warp GEMM: 32(m) x 64(n), 3 split passes ----
    const int mrow = wid >> 1;
    const int ncol = wid & 1;

    float acc[2][8][4];
    #pragma unroll
    for (int mt = 0; mt < 2; mt++)
        #pragma unroll
        for (int nt = 0; nt < 8; nt++)
            #pragma unroll
            for (int c = 0; c < 4; c++) acc[mt][nt][c] = 0.f;

    const uint32_t abase[3] = { sb + SM_QHI, sb + SM_QHI, sb + SM_QLO };
    const uint32_t bbase[3] = { sb + SM_KHI, sb + SM_KLO, sb + SM_KHI };

    #pragma unroll
    for (int pass = 0; pass < 3; pass++) {
        #pragma unroll
        for (int ks16 = 0; ks16 < 4; ks16++) {
            const uint32_t dby = ks16 * 32;
            uint32_t a[2][4];
            #pragma unroll
            for (int mt = 0; mt < 2; mt++) {
                uint32_t addr = abase[pass]
                    + (uint32_t)(mrow * 32 + mt * 16 + (lane & 15)) * TSTRIDE_B
                    + dby + ((lane >> 4) << 4);
                ldsm_x4(a[mt][0], a[mt][1], a[mt][2], a[mt][3], addr);
            }
            uint32_t b[8][2];
            #pragma unroll
            for (int np = 0; np < 4; np++) {
                uint32_t n = (uint32_t)(ncol * 64 + np * 16 + ((lane >> 4) << 3) + (lane & 7));
                uint32_t addr = bbase[pass] + n * TSTRIDE_B + dby + (((lane >> 3) & 1) << 4);
                ldsm_x4(b[np * 2][0], b[np * 2][1], b[np * 2 + 1][0], b[np * 2 + 1][1], addr);
            }
            #pragma unroll
            for (int mt = 0; mt < 2; mt++)
                #pragma unroll
                for (int nt = 0; nt < 8; nt++)
                    mma_bf16(acc[mt][nt][0], acc[mt][nt][1], acc[mt][nt][2], acc[mt][nt][3],
                             a[mt][0], a[mt][1], a[mt][2], a[mt][3],
                             b[nt][0], b[nt][1]);
        }
    }

    // ---- branch-free epilogue: per-row min of (ksq - 2*dot) over 64 cols ----
    {
        const int g = lane >> 2, t = lane & 3;
        float rm[4];
        #pragma unroll
        for (int mt = 0; mt < 2; mt++) {
            float m0 = CUDART_INF_F, m1 = CUDART_INF_F;
            #pragma unroll
            for (int nt = 0; nt < 8; nt++) {
                const int col = ncol * 64 + nt * 8 + t * 2;
                const float kq0 = ksq[col], kq1 = ksq[col + 1];
                m0 = fminf(m0, fminf(fmaf(-2.f, acc[mt][nt][0], kq0),
                                     fmaf(-2.f, acc[mt][nt][1], kq1)));
                m1 = fminf(m1, fminf(fmaf(-2.f, acc[mt][nt][2], kq0),
                                     fmaf(-2.f, acc[mt][nt][3], kq1)));
            }
            rm[mt * 2] = m0; rm[mt * 2 + 1] = m1;
        }
        #pragma unroll
        for (int r = 0; r < 4; r++) {
            rm[r] = fminf(rm[r], __shfl_xor_sync(0xFFFFFFFFu, rm[r], 1));
            rm[r] = fminf(rm[r], __shfl_xor_sync(0xFFFFFFFFu, rm[r], 2));
        }
        if (t == 0) {
            const int half = blockIdx.x * 2 + ncol;
            const int rowb = q0 + mrow * 32 + g;
            g_hmin[(size_t)(rowb)      * NHP + half] = rm[0];
            g_hmin[(size_t)(rowb + 8)  * NHP + half] = rm[1];
            g_hmin[(size_t)(rowb + 16) * NHP + half] = rm[2];
            g_hmin[(size_t)(rowb + 24) * NHP + half] = rm[3];
        }
    }
}

// ======================================================================
// Kernel 2: per-query 8th-smallest half-min -> cutoff -> compact halves
// grid NQ, 256 threads
// ======================================================================
__global__ __launch_bounds__(256) void knn_threshold()
{
    __shared__ float ms[256 * 8];
    __shared__ float s_cut;
    __shared__ int   s_cnt;
    const int q = blockIdx.x, tid = threadIdx.x;

    float l[8];
    #pragma unroll
    for (int i = 0; i < 8; i++) l[i] = CUDART_INF_F;

    #pragma unroll
    for (int r = 0; r < 4; r++) {
        const int h = tid + r * 256;
        if (h < NHALF) {
            float s = g_hmin[(size_t)q * NHP + h];
            if (s < l[7]) {
                l[7] = s;
                #pragma unroll
                for (int u = 7; u > 0; u--)
                    if (l[u] < l[u-1]) { float ts = l[u]; l[u] = l[u-1]; l[u-1] = ts; }
            }
        }
    }
    #pragma unroll
    for (int m = 0; m < 8; m++) ms[tid * 8 + m] = l[m];

    for (int st = 128; st >= 1; st >>= 1) {
        __syncthreads();
        if (tid < st) {
            const int o = (tid + st) * 8;
            #pragma unroll 1
            for (int m = 0; m < 8; m++) {
                float s = ms[o + m];
                if (s >= l[7]) break;
                l[7] = s;
                #pragma unroll
                for (int u = 7; u > 0; u--)
                    if (l[u] < l[u-1]) { float ts = l[u]; l[u] = l[u-1]; l[u-1] = ts; }
            }
            #pragma unroll
            for (int m = 0; m < 8; m++) ms[tid * 8 + m] = l[m];
        }
    }
    if (tid == 0) { s_cut = l[7] + MARGIN; s_cnt = 0; }
    __syncthreads();

    const float cut = s_cut;
    #pragma unroll
    for (int r = 0; r < 4; r++) {
        const int h = tid + r * 256;
        if (h < NHALF && g_hmin[(size_t)q * NHP + h] <= cut) {
            int p = atomicAdd(&s_cnt, 1);
            if (p < CAP) g_candlist[q * CAP + p] = h;
        }
    }
    __syncthreads();
    if (tid == 0) g_candcnt[q] = (s_cnt < CAP) ? s_cnt : CAP;
}

// ======================================================================
// Kernel 3: exact fp32 rescore of candidate halves -> exact top-8
// grid NQ, 256 threads
// ======================================================================
__global__ __launch_bounds__(256) void knn_rescore(
    const float* __restrict__ qm, const float* __restrict__ km)
{
    __shared__ float qs[64];
    __shared__ float ms[256 * 8];
    __shared__ int   mi[256 * 8];
    const int q = blockIdx.x, tid = threadIdx.x;

    if (tid < 64) qs[tid] = qm[(size_t)q * DD + tid];
    __syncthreads();

    const int cnt = g_candcnt[q];
    float l[8]; int li[8];
    #pragma unroll
    for (int i = 0; i < 8; i++) { l[i] = CUDART_INF_F; li[i] = 0x7FFFFFFF; }

    const float4* qp = (const float4*)qs;
    for (int i = tid >> 6; i < cnt; i += 4) {
        const int j = g_candlist[q * CAP + i] * 64 + (tid & 63);
        if (j < NK) {
            const float4* kp = (const float4*)(km + (size_t)j * DD);
            float dot = 0.f, ks = 0.f;
            #pragma unroll
            for (int w = 0; w < 16; w++) {
                float4 kv = kp[w];
                float4 qv = qp[w];
                dot = fmaf(kv.x, qv.x, dot); ks = fmaf(kv.x, kv.x, ks);
                dot = fmaf(kv.y, qv.y, dot); ks = fmaf(kv.y, kv.y, ks);
                dot = fmaf(kv.z, qv.z, dot); ks = fmaf(kv.z, kv.z, ks);
                dot = fmaf(kv.w, qv.w, dot); ks = fmaf(kv.w, kv.w, ks);
            }
            float s = fmaf(-2.f, dot, ks);
            INS8T(s, j);
        }
    }
    #pragma unroll
    for (int m = 0; m < 8; m++) { ms[tid * 8 + m] = l[m]; mi[tid * 8 + m] = li[m]; }

    for (int st = 128; st >= 1; st >>= 1) {
        __syncthreads();
        if (tid < st) {
            const int o = (tid + st) * 8;
            #pragma unroll 1
            for (int m = 0; m < 8; m++) {
                float s = ms[o + m];
                int   j = mi[o + m];
                bool better = (s < l[7]) || (s == l[7] && j < li[7]);
                if (!better) break;
                l[7] = s; li[7] = j;
                #pragma unroll
                for (int u = 7; u > 0; u--)
                    if (l[u] < l[u-1] || (l[u] == l[u-1] && li[u] < li[u-1])) {
                        float ts = l[u]; l[u] = l[u-1]; l[u-1] = ts;
                        int ti = li[u]; li[u] = li[u-1]; li[u-1] = ti;
                    }
            }
            #pragma unroll
            for (int m = 0; m < 8; m++) { ms[tid * 8 + m] = l[m]; mi[tid * 8 + m] = li[m]; }
        }
    }
    if (tid == 0) {
        #pragma unroll
        for (int m = 0; m < 8; m++) g_topidx[q * 8 + m] = li[m];
    }
}

// ======================================================================
// Kernel 4: gather obs[idx] -> out [8, 256, 3072]
// ======================================================================
__global__ __launch_bounds__(256) void knn_gather_kernel(
    const float* __restrict__ obs, float* __restrict__ out)
{
    const int b  = blockIdx.x;
    const int kk = b >> 8;
    const int q  = b & 255;
    const int src = g_topidx[q * 8 + kk];

    const float4* s = (const float4*)(obs + (size_t)src * OBS_ELEMS);
    float4*       d = (float4*)(out + ((size_t)kk * NQ + q) * OBS_ELEMS);

    #pragma unroll
    for (int i = threadIdx.x; i < OBS_ELEMS / 4; i += 256)
        d[i] = s[i];
}

// ======================================================================
extern "C" void kernel_launch(void* const* d_in, const int* in_sizes, int n_in,
                              void* d_out, int out_size)
{
    const float* q   = (const float*)d_in[0];
    const float* k   = (const float*)d_in[1];
    const float* obs = (const float*)d_in[2];
    float* out = (float*)d_out;

    cudaFuncSetAttribute(knn_score_min,
                         cudaFuncAttributeMaxDynamicSharedMemorySize, SM_TOTAL);

    knn_score_min<<<dim3(NKT, 2), 256, SM_TOTAL>>>(q, k);
    knn_threshold<<<NQ, 256>>>();
    knn_rescore<<<NQ, 256>>>(q, k);
    knn_gather_kernel<<<NQ * 8, 256>>>(obs, out);
}